// round 16
// baseline (speedup 1.0000x reference)
#include <cuda_runtime.h>

#define NTHR  128      // threads per block
#define NPT   256      // points per block (2 per thread)
#define DIM   65
#define NA    16
#define ASTR  68
#define ALPHA 0.1f
#define EPSF  1e-7f

typedef unsigned long long u64;

// Anchor s-parts, densely repacked [NA][64], 16B-aligned rows -> uniform LDC.128
__constant__ float c_anch_s[NA * 64];

// ---- f32x2 packed helpers (sm_103a) ----
__device__ __forceinline__ u64 pk(float lo, float hi) {
    u64 r; asm("mov.b64 %0, {%1,%2};" : "=l"(r) : "f"(lo), "f"(hi)); return r;
}
__device__ __forceinline__ void upk(u64 v, float& lo, float& hi) {
    asm("mov.b64 {%0,%1}, %2;" : "=f"(lo), "=f"(hi) : "l"(v));
}
__device__ __forceinline__ u64 ffma2(u64 a, u64 b, u64 c) {
    u64 d; asm("fma.rn.f32x2 %0, %1, %2, %3;" : "=l"(d) : "l"(a), "l"(b), "l"(c)); return d;
}
__device__ __forceinline__ u64 fmul2(u64 a, u64 b) {
    u64 d; asm("mul.rn.f32x2 %0, %1, %2;" : "=l"(d) : "l"(a), "l"(b)); return d;
}
__device__ __forceinline__ unsigned s2u(const void* p) {
    unsigned a;
    asm("{ .reg .u64 t; cvta.to.shared.u64 t, %1; cvt.u32.u64 %0, t; }" : "=r"(a) : "l"(p));
    return a;
}
// ---- MUFU approx helpers ----
__device__ __forceinline__ float sqrt_ap(float x){ float r; asm("sqrt.approx.f32 %0, %1;" : "=f"(r) : "f"(x)); return r; }
__device__ __forceinline__ float rcp_ap (float x){ float r; asm("rcp.approx.f32 %0, %1;"  : "=f"(r) : "f"(x)); return r; }
__device__ __forceinline__ float lg2_ap (float x){ float r; asm("lg2.approx.f32 %0, %1;"  : "=f"(r) : "f"(x)); return r; }
__device__ __forceinline__ float ex2_ap (float x){ float r; asm("ex2.approx.f32 %0, %1;"  : "=f"(r) : "f"(x)); return r; }

#define TILE_BYTES (NPT * DIM * 4)   // 66560, %16 == 0

// Argmin + MUFU scalar chain + vector writeback for one point (anchors from smem: divergent index).
__device__ __forceinline__ void finish_point(const u64* acc, float* row, float h0,
                                             const float* anch, bool valid)
{
    float best_z = 3.4e38f, best_inner = 0.f;
    int best_a = 0;
    #pragma unroll
    for (int a = 0; a < NA; a++) {
        float x0, x1; upk(acc[a], x0, x1);
        float inner = x0 + x1;
        float z = fmaxf(-inner, 1.0f + EPSF);
        if (z < best_z) { best_z = z; best_inner = inner; best_a = a; }
    }
    const float xy = best_inner, zc = best_z;
    const float* bb = anch + best_a * ASTR;
    const float at = bb[64];

    // uu = linner(u,u) = xy^2 - 1 (hyperboloid identity); acosh(z) = ln(z + sqrt(z^2-1))
    float uu    = fmaf(xy, xy, -1.0f);
    float w     = sqrt_ap(fmaxf(uu, EPSF));
    float d     = 0.69314718056f * lg2_ap(zc + w);
    float scale = (ALPHA * d) * rcp_ap(w);
    float vv    = scale * scale * uu;
    float vn    = sqrt_ap(fmaxf(vv, EPSF * EPSF));
    float e     = ex2_ap(vn * 1.44269504089f);
    float ei    = rcp_ap(e);
    float ch    = 0.5f * (e + ei);
    float sh    = 0.5f * (e - ei);
    float sinhc = (vn > EPSF) ? sh * rcp_ap(vn) : 1.0f;
    float s2    = sinhc * scale;
    float c1    = fmaf(s2, xy, ch);              // out = c1*h + s2*na

    if (valid) {
        row[0] = fmaf(c1, h0, s2 * at);
        u64 c1v = pk(c1, c1), s2v = pk(s2, s2);
        const ulonglong2* av = (const ulonglong2*)bb;
        #pragma unroll
        for (int q = 0; q < 16; q++) {
            ulonglong2 v = av[q];
            u64 hL = pk(row[1 + 4 * q], row[2 + 4 * q]);
            u64 hH = pk(row[3 + 4 * q], row[4 + 4 * q]);
            u64 oL = ffma2(c1v, hL, fmul2(s2v, v.x));
            u64 oH = ffma2(c1v, hH, fmul2(s2v, v.y));
            float a0, a1, b0, b1; upk(oL, a0, a1); upk(oH, b0, b1);
            row[1 + 4 * q] = a0; row[2 + 4 * q] = a1;
            row[3 + 4 * q] = b0; row[4 + 4 * q] = b1;
        }
    }
}

__global__ __launch_bounds__(NTHR, 3)
void hfh_kernel(const float* __restrict__ hyp, float* __restrict__ out, int B)
{
    extern __shared__ float smem[];
    float* tile = smem;                       // NPT*DIM floats, row stride 65 (conflict-free)
    float* anch = smem + NPT * DIM;           // NA*ASTR floats: [s0..s63, a_t, -a_t, pad, pad]
    u64*   mbar = (u64*)(smem + NPT * DIM + NA * ASTR);

    const int tid = threadIdx.x;
    const long long p0 = (long long)blockIdx.x * NPT;
    const int n = min(NPT, B - (int)p0);
    const bool full = (n == NPT);
    const unsigned tile_sm = s2u(tile);
    const unsigned mbar_sm = s2u(mbar);

    // ---- Start async tile load (full blocks) ----
    if (full) {
        if (tid == 0) {
            asm volatile("mbarrier.init.shared.b64 [%0], %1;" :: "r"(mbar_sm), "r"(1) : "memory");
        }
        __syncthreads();
        if (tid == 0) {
            asm volatile("mbarrier.arrive.expect_tx.shared.b64 _, [%0], %1;"
                         :: "r"(mbar_sm), "r"(TILE_BYTES) : "memory");
            asm volatile("cp.async.bulk.shared::cta.global.mbarrier::complete_tx::bytes "
                         "[%0], [%1], %2, [%3];"
                         :: "r"(tile_sm), "l"(hyp + p0 * DIM), "r"(TILE_BYTES), "r"(mbar_sm)
                         : "memory");
        }
    } else {
        const float* src = hyp + p0 * DIM;
        for (int i = tid; i < n * DIM; i += NTHR) tile[i] = src[i];
    }

    // ---- Anchor prep (smem copy for divergent epilogue access) overlapped with TMA ----
    if (tid < NA) {
        float* ar = anch + tid * ASTR;
        const float* ga = c_anch_s + tid * 64;
        float ss = 0.f;
        #pragma unroll
        for (int k = 0; k < 64; k++) { float v = ga[k]; ar[k] = v; ss = fmaf(v, v, ss); }
        float at = sqrtf(1.0f + ss);
        ar[64] = at; ar[65] = -at; ar[66] = 0.f; ar[67] = 0.f;
    }
    __syncthreads();

    if (full) {
        asm volatile(
            "{\n\t.reg .pred P;\n\t"
            "WL_%=:\n\t"
            "mbarrier.try_wait.parity.acquire.cta.shared::cta.b64 P, [%0], 0, 0x989680;\n\t"
            "@P bra.uni WD_%=;\n\t"
            "bra.uni WL_%=;\n\t"
            "WD_%=:\n\t}"
            :: "r"(mbar_sm) : "memory");
    }

    // ---- 2 points per thread ----
    const bool vA = tid < n;
    const bool vB = (tid + NTHR) < n;
    float* rowA = vA ? (tile + tid * DIM) : tile;             // invalid -> row 0 (finite dummy)
    float* rowB = vB ? (tile + (tid + NTHR) * DIM) : tile;
    const float h0A = rowA[0];
    const float h0B = rowB[0];

    u64 accA[NA], accB[NA];
    #pragma unroll
    for (int a = 0; a < NA; a++) {
        float atn = anch[a * ASTR + 65];                      // -a_t (broadcast LDS)
        accA[a] = pk(h0A * atn, 0.f);
        accB[a] = pk(h0B * atn, 0.f);
    }

    // Anchor FMA loop in two 32-dim chunks.
    // Anchor values come from the CONSTANT port (uniform LDC.128) -> zero l1tex traffic.
    // ulonglong2 = 4 floats, so a 32-float chunk spans 8 ulonglong2 -> offset 8*c.
    // Pairing: av[q] covers floats {4q..4q+3} == packed pairs hA[2q], hA[2q+1].
    #pragma unroll
    for (int c = 0; c < 2; c++) {
        u64 hA[16], hB[16];
        const float* ra = rowA + 1 + 32 * c;
        const float* rb = rowB + 1 + 32 * c;
        #pragma unroll
        for (int j = 0; j < 16; j++) {
            hA[j] = pk(ra[2 * j], ra[2 * j + 1]);
            hB[j] = pk(rb[2 * j], rb[2 * j + 1]);
        }
        #pragma unroll
        for (int a = 0; a < NA; a++) {
            const ulonglong2* av = (const ulonglong2*)(c_anch_s + a * 64) + 8 * c;
            #pragma unroll
            for (int q = 0; q < 8; q++) {
                ulonglong2 v = av[q];                         // LDC.128, uniform address
                accA[a] = ffma2(hA[2 * q],     v.x, accA[a]);
                accA[a] = ffma2(hA[2 * q + 1], v.y, accA[a]);
                accB[a] = ffma2(hB[2 * q],     v.x, accB[a]);
                accB[a] = ffma2(hB[2 * q + 1], v.y, accB[a]);
            }
        }
    }

    finish_point(accA, rowA, h0A, anch, vA);
    finish_point(accB, rowB, h0B, anch, vB);

    __syncthreads();

    // ---- Bulk writeout ----
    if (full) {
        if (tid == 0) {
            asm volatile("fence.proxy.async.shared::cta;" ::: "memory");
            asm volatile("cp.async.bulk.global.shared::cta.bulk_group [%0], [%1], %2;"
                         :: "l"(out + p0 * DIM), "r"(tile_sm), "r"(TILE_BYTES) : "memory");
            asm volatile("cp.async.bulk.commit_group;" ::: "memory");
            asm volatile("cp.async.bulk.wait_group 0;" ::: "memory");
        }
    } else {
        float* dst = out + p0 * DIM;
        for (int i = tid; i < n * DIM; i += NTHR) dst[i] = tile[i];
    }
}

extern "C" void kernel_launch(void* const* d_in, const int* in_sizes, int n_in,
                              void* d_out, int out_size)
{
    const float* hyp = (const float*)d_in[0];
    const char* anc = (const char*)d_in[1];
    float* out = (float*)d_out;
    const int B = in_sizes[0] / DIM;
    const int grid = (B + NPT - 1) / NPT;

    // Repack anchor s-parts [NA][64] (src pitch 260B, skipping the leading a_t)
    // into the dense 256B-row __constant__ buffer. cudaGetSymbolAddress is a
    // host-side query (no allocation); cudaMemcpy2DAsync D2D is graph-capturable.
    void* c_ptr = nullptr;
    cudaGetSymbolAddress(&c_ptr, c_anch_s);
    cudaMemcpy2DAsync(c_ptr, (size_t)64 * 4,
                      anc + 4, (size_t)DIM * 4,
                      (size_t)64 * 4, (size_t)NA,
                      cudaMemcpyDeviceToDevice, 0);

    const size_t shmem = (size_t)(NPT * DIM + NA * ASTR) * sizeof(float) + 16;
    cudaFuncSetAttribute(hfh_kernel, cudaFuncAttributeMaxDynamicSharedMemorySize, (int)shmem);
    hfh_kernel<<<grid, NTHR, shmem>>>(hyp, out, B);
}

// round 17
// speedup vs baseline: 7.1057x; 7.1057x over previous
#include <cuda_runtime.h>

#define NTHR  128      // threads per block
#define NPT   256      // points per block (2 per thread)
#define DIM   65
#define NA    16
#define ALPHA 0.1f
#define EPSF  1e-7f

typedef unsigned long long u64;

// ---- f32x2 packed helpers (sm_103a) ----
__device__ __forceinline__ u64 pk(float lo, float hi) {
    u64 r; asm("mov.b64 %0, {%1,%2};" : "=l"(r) : "f"(lo), "f"(hi)); return r;
}
__device__ __forceinline__ void upk(u64 v, float& lo, float& hi) {
    asm("mov.b64 {%0,%1}, %2;" : "=f"(lo), "=f"(hi) : "l"(v));
}
__device__ __forceinline__ u64 ffma2(u64 a, u64 b, u64 c) {
    u64 d; asm("fma.rn.f32x2 %0, %1, %2, %3;" : "=l"(d) : "l"(a), "l"(b), "l"(c)); return d;
}
__device__ __forceinline__ u64 fmul2(u64 a, u64 b) {
    u64 d; asm("mul.rn.f32x2 %0, %1, %2;" : "=l"(d) : "l"(a), "l"(b)); return d;
}
__device__ __forceinline__ unsigned s2u(const void* p) {
    unsigned a;
    asm("{ .reg .u64 t; cvta.to.shared.u64 t, %1; cvt.u32.u64 %0, t; }" : "=r"(a) : "l"(p));
    return a;
}
// ---- MUFU approx helpers ----
__device__ __forceinline__ float sqrt_ap(float x){ float r; asm("sqrt.approx.f32 %0, %1;" : "=f"(r) : "f"(x)); return r; }
__device__ __forceinline__ float rcp_ap (float x){ float r; asm("rcp.approx.f32 %0, %1;"  : "=f"(r) : "f"(x)); return r; }
__device__ __forceinline__ float lg2_ap (float x){ float r; asm("lg2.approx.f32 %0, %1;"  : "=f"(r) : "f"(x)); return r; }
__device__ __forceinline__ float ex2_ap (float x){ float r; asm("ex2.approx.f32 %0, %1;"  : "=f"(r) : "f"(x)); return r; }

#define TILE_BYTES (NPT * DIM * 4)   // 66560, %16 == 0
// anchT layout (floats): [j=0..15][a=0..15][k=0..3] = anch[a].s[4j+k]  (16 rows x 256B)
// then at_pos[16] @ offset 1024, at_neg[16] @ offset 1040. Total 1056 floats.
#define ATF 1056

// Argmin + MUFU scalar chain + vector writeback for one point.
// Divergent anchor access goes through the TRANSPOSED layout: per j-load the 16
// anchors occupy 16 distinct 16B slots in one 256B row -> 2 wavefronts, no replay.
__device__ __forceinline__ void finish_point(const u64* acc, float* row, float h0,
                                             const float* anchT, bool valid)
{
    float best_z = 3.4e38f, best_inner = 0.f;
    int best_a = 0;
    #pragma unroll
    for (int a = 0; a < NA; a++) {
        float x0, x1; upk(acc[a], x0, x1);
        float inner = x0 + x1;
        float z = fmaxf(-inner, 1.0f + EPSF);
        if (z < best_z) { best_z = z; best_inner = inner; best_a = a; }
    }
    const float xy = best_inner, zc = best_z;
    const float at = anchT[1024 + best_a];     // conflict-free (16 consecutive floats)

    // uu = linner(u,u) = xy^2 - 1 (hyperboloid identity); acosh(z) = ln(z + sqrt(z^2-1))
    float uu    = fmaf(xy, xy, -1.0f);
    float w     = sqrt_ap(fmaxf(uu, EPSF));
    float d     = 0.69314718056f * lg2_ap(zc + w);
    float scale = (ALPHA * d) * rcp_ap(w);
    float vv    = scale * scale * uu;
    float vn    = sqrt_ap(fmaxf(vv, EPSF * EPSF));
    float e     = ex2_ap(vn * 1.44269504089f);
    float ei    = rcp_ap(e);
    float ch    = 0.5f * (e + ei);
    float sh    = 0.5f * (e - ei);
    float sinhc = (vn > EPSF) ? sh * rcp_ap(vn) : 1.0f;
    float s2    = sinhc * scale;
    float c1    = fmaf(s2, xy, ch);            // out = c1*h + s2*na

    if (valid) {
        row[0] = fmaf(c1, h0, s2 * at);
        u64 c1v = pk(c1, c1), s2v = pk(s2, s2);
        #pragma unroll
        for (int q = 0; q < 16; q++) {
            ulonglong2 v = *(const ulonglong2*)(anchT + q * 64 + best_a * 4);
            u64 hL = pk(row[1 + 4 * q], row[2 + 4 * q]);
            u64 hH = pk(row[3 + 4 * q], row[4 + 4 * q]);
            u64 oL = ffma2(c1v, hL, fmul2(s2v, v.x));
            u64 oH = ffma2(c1v, hH, fmul2(s2v, v.y));
            float a0, a1, b0, b1; upk(oL, a0, a1); upk(oH, b0, b1);
            row[1 + 4 * q] = a0; row[2 + 4 * q] = a1;
            row[3 + 4 * q] = b0; row[4 + 4 * q] = b1;
        }
    }
}

__global__ __launch_bounds__(NTHR, 3)
void hfh_kernel(const float* __restrict__ hyp, const float* __restrict__ anchors,
                float* __restrict__ out, int B)
{
    extern __shared__ float smem[];
    float* tile  = smem;                      // NPT*DIM floats, row stride 65 (conflict-free)
    float* anchT = smem + NPT * DIM;          // ATF floats (transposed anchors + at rows)
    u64*   mbar  = (u64*)(smem + NPT * DIM + ATF);

    const int tid = threadIdx.x;
    const long long p0 = (long long)blockIdx.x * NPT;
    const int n = min(NPT, B - (int)p0);
    const bool full = (n == NPT);
    const unsigned tile_sm = s2u(tile);
    const unsigned mbar_sm = s2u(mbar);

    // ---- Start async tile load (full blocks) ----
    if (full) {
        if (tid == 0) {
            asm volatile("mbarrier.init.shared.b64 [%0], %1;" :: "r"(mbar_sm), "r"(1) : "memory");
        }
        __syncthreads();
        if (tid == 0) {
            asm volatile("mbarrier.arrive.expect_tx.shared.b64 _, [%0], %1;"
                         :: "r"(mbar_sm), "r"(TILE_BYTES) : "memory");
            asm volatile("cp.async.bulk.shared::cta.global.mbarrier::complete_tx::bytes "
                         "[%0], [%1], %2, [%3];"
                         :: "r"(tile_sm), "l"(hyp + p0 * DIM), "r"(TILE_BYTES), "r"(mbar_sm)
                         : "memory");
        }
    } else {
        const float* src = hyp + p0 * DIM;
        for (int i = tid; i < n * DIM; i += NTHR) tile[i] = src[i];
    }

    // ---- Anchor prep into TRANSPOSED smem layout, overlapped with the TMA ----
    if (tid < NA) {
        const float* ga = anchors + tid * DIM + 1;
        float ss = 0.f;
        #pragma unroll
        for (int k = 0; k < 64; k++) {
            float v = ga[k];
            anchT[(k >> 2) * 64 + tid * 4 + (k & 3)] = v;
            ss = fmaf(v, v, ss);
        }
        float at = sqrtf(1.0f + ss);
        anchT[1024 + tid] = at;
        anchT[1040 + tid] = -at;
    }
    __syncthreads();

    if (full) {
        asm volatile(
            "{\n\t.reg .pred P;\n\t"
            "WL_%=:\n\t"
            "mbarrier.try_wait.parity.acquire.cta.shared::cta.b64 P, [%0], 0, 0x989680;\n\t"
            "@P bra.uni WD_%=;\n\t"
            "bra.uni WL_%=;\n\t"
            "WD_%=:\n\t}"
            :: "r"(mbar_sm) : "memory");
    }

    // ---- 2 points per thread ----
    const bool vA = tid < n;
    const bool vB = (tid + NTHR) < n;
    float* rowA = vA ? (tile + tid * DIM) : tile;             // invalid -> row 0 (finite dummy)
    float* rowB = vB ? (tile + (tid + NTHR) * DIM) : tile;
    const float h0A = rowA[0];
    const float h0B = rowB[0];

    u64 accA[NA], accB[NA];
    #pragma unroll
    for (int a = 0; a < NA; a++) {
        float atn = anchT[1040 + a];                          // -a_t (broadcast LDS)
        accA[a] = pk(h0A * atn, 0.f);
        accB[a] = pk(h0B * atn, 0.f);
    }

    // Anchor FMA loop in two 32-dim chunks (8 j-rows of 4 dims each).
    // Uniform (broadcast) LDS.128 from the transposed layout; each feeds 4 ffma2.
    #pragma unroll
    for (int c = 0; c < 2; c++) {
        u64 hA[16], hB[16];
        const float* ra = rowA + 1 + 32 * c;
        const float* rb = rowB + 1 + 32 * c;
        #pragma unroll
        for (int j = 0; j < 16; j++) {
            hA[j] = pk(ra[2 * j], ra[2 * j + 1]);
            hB[j] = pk(rb[2 * j], rb[2 * j + 1]);
        }
        #pragma unroll
        for (int a = 0; a < NA; a++) {
            #pragma unroll
            for (int q = 0; q < 8; q++) {
                ulonglong2 v = *(const ulonglong2*)(anchT + (8 * c + q) * 64 + a * 4);
                accA[a] = ffma2(hA[2 * q],     v.x, accA[a]);
                accA[a] = ffma2(hA[2 * q + 1], v.y, accA[a]);
                accB[a] = ffma2(hB[2 * q],     v.x, accB[a]);
                accB[a] = ffma2(hB[2 * q + 1], v.y, accB[a]);
            }
        }
    }

    finish_point(accA, rowA, h0A, anchT, vA);
    finish_point(accB, rowB, h0B, anchT, vB);

    __syncthreads();

    // ---- Bulk writeout ----
    if (full) {
        if (tid == 0) {
            asm volatile("fence.proxy.async.shared::cta;" ::: "memory");
            asm volatile("cp.async.bulk.global.shared::cta.bulk_group [%0], [%1], %2;"
                         :: "l"(out + p0 * DIM), "r"(tile_sm), "r"(TILE_BYTES) : "memory");
            asm volatile("cp.async.bulk.commit_group;" ::: "memory");
            asm volatile("cp.async.bulk.wait_group 0;" ::: "memory");
        }
    } else {
        float* dst = out + p0 * DIM;
        for (int i = tid; i < n * DIM; i += NTHR) dst[i] = tile[i];
    }
}

extern "C" void kernel_launch(void* const* d_in, const int* in_sizes, int n_in,
                              void* d_out, int out_size)
{
    const float* hyp = (const float*)d_in[0];
    const float* anc = (const float*)d_in[1];
    float* out = (float*)d_out;
    const int B = in_sizes[0] / DIM;
    const int grid = (B + NPT - 1) / NPT;
    const size_t shmem = (size_t)(NPT * DIM + ATF) * sizeof(float) + 16;   // 70,800 B
    cudaFuncSetAttribute(hfh_kernel, cudaFuncAttributeMaxDynamicSharedMemorySize, (int)shmem);
    hfh_kernel<<<grid, NTHR, shmem>>>(hyp, anc, out, B);
}